// round 2
// baseline (speedup 1.0000x reference)
#include <cuda_runtime.h>
#include <cuda_bf16.h>

// Problem dims
#define BDIM 65536
#define HDIM 1024
#define SDIM 1024
#define DDIM 128
#define LODIM 2048   // 2*SDIM : [read logits | write logits] per row

// ---------------- scratch (device globals: allocation-free rule) ----------------
__device__ float g_logits[(size_t)BDIM * LODIM];   // 512 MB, reused in-place for softmax weights
__device__ float g_part[256 * 1024];               // partial column sums
__device__ float g_cmean_h[HDIM];                  // mean(content) over B
__device__ float g_wmean[SDIM];                    // mean write weights
__device__ float g_cvec[DDIM];                     // c_mean = mean(content) @ W_content + b

// ---------------- reductions ----------------
__device__ __forceinline__ float warpMax(float v) {
    #pragma unroll
    for (int o = 16; o > 0; o >>= 1) v = fmaxf(v, __shfl_xor_sync(0xffffffffu, v, o));
    return v;
}
__device__ __forceinline__ float warpSum(float v) {
    #pragma unroll
    for (int o = 16; o > 0; o >>= 1) v += __shfl_xor_sync(0xffffffffu, v, o);
    return v;
}

// ============================================================================
// K1: logits = query @ [W_read | W_write] + bias   (65536 x 2048, K=1024)
// 128x128 tile, BK=16, 256 threads, 8x8 per thread.
// bx in [0,8): read columns; bx in [8,16): write columns. outcol0 = bx*128.
// ============================================================================
__global__ __launch_bounds__(256) void gemm_logits_kernel(
    const float* __restrict__ Q,
    const float* __restrict__ Wr, const float* __restrict__ Ww,
    const float* __restrict__ br, const float* __restrict__ bw)
{
    __shared__ float As[16][132];   // [k][m], padded to kill STS bank conflicts
    __shared__ float Bs[16][128];   // [k][n]

    const int bx = blockIdx.x, by = blockIdx.y;
    const float* W;  const float* bias;  int n0;
    if (bx < 8) { W = Wr; bias = br; n0 = bx * 128; }
    else        { W = Ww; bias = bw; n0 = (bx - 8) * 128; }
    const int m0 = by * 128;

    const int tid = threadIdx.x;
    const int tx = tid & 15, ty = tid >> 4;          // 16x16 threads, each 8x8

    const int arow = tid >> 2;                       // 0..63 (+64)
    const int acol = (tid & 3) * 4;                  // 0,4,8,12
    const int brow = tid >> 5;                       // 0..7 (+8)
    const int bcol = (tid & 31) * 4;                 // 0..124

    const float* Aptr = Q + (size_t)m0 * HDIM;
    const float* Bptr = W + n0;

    float acc[8][8];
    #pragma unroll
    for (int i = 0; i < 8; ++i)
        #pragma unroll
        for (int j = 0; j < 8; ++j) acc[i][j] = 0.f;

    for (int k0 = 0; k0 < HDIM; k0 += 16) {
        #pragma unroll
        for (int h = 0; h < 2; ++h) {
            float4 v = *reinterpret_cast<const float4*>(
                Aptr + (size_t)(arow + 64 * h) * HDIM + k0 + acol);
            As[acol + 0][arow + 64 * h] = v.x;
            As[acol + 1][arow + 64 * h] = v.y;
            As[acol + 2][arow + 64 * h] = v.z;
            As[acol + 3][arow + 64 * h] = v.w;
        }
        #pragma unroll
        for (int h = 0; h < 2; ++h) {
            float4 v = *reinterpret_cast<const float4*>(
                Bptr + (size_t)(k0 + brow + 8 * h) * SDIM + bcol);
            *reinterpret_cast<float4*>(&Bs[brow + 8 * h][bcol]) = v;
        }
        __syncthreads();
        #pragma unroll
        for (int k = 0; k < 16; ++k) {
            float4 a0 = *reinterpret_cast<const float4*>(&As[k][ty * 8]);
            float4 a1 = *reinterpret_cast<const float4*>(&As[k][ty * 8 + 4]);
            float4 b0 = *reinterpret_cast<const float4*>(&Bs[k][tx * 8]);
            float4 b1 = *reinterpret_cast<const float4*>(&Bs[k][tx * 8 + 4]);
            float a[8] = {a0.x, a0.y, a0.z, a0.w, a1.x, a1.y, a1.z, a1.w};
            float b[8] = {b0.x, b0.y, b0.z, b0.w, b1.x, b1.y, b1.z, b1.w};
            #pragma unroll
            for (int i = 0; i < 8; ++i)
                #pragma unroll
                for (int j = 0; j < 8; ++j)
                    acc[i][j] += a[i] * b[j];
        }
        __syncthreads();
    }

    const int outcol0 = bx * 128 + tx * 8;
    const int wcol0   = n0 + tx * 8;
    #pragma unroll
    for (int i = 0; i < 8; ++i) {
        float* orow = g_logits + (size_t)(m0 + ty * 8 + i) * LODIM + outcol0;
        #pragma unroll
        for (int j = 0; j < 8; ++j)
            orow[j] = acc[i][j] + bias[wcol0 + j];
    }
}

// ============================================================================
// K2: in-place softmax over each 1024-wide half of every logits row.
// One block (256 threads) per row.
// ============================================================================
__global__ __launch_bounds__(256) void softmax_kernel()
{
    __shared__ float red[8];
    float* base = g_logits + (size_t)blockIdx.x * LODIM;
    const int t = threadIdx.x;

    #pragma unroll
    for (int half = 0; half < 2; ++half) {
        float* x = base + half * SDIM;
        float v0 = x[t], v1 = x[t + 256], v2 = x[t + 512], v3 = x[t + 768];

        float m = fmaxf(fmaxf(v0, v1), fmaxf(v2, v3));
        m = warpMax(m);
        if ((t & 31) == 0) red[t >> 5] = m;
        __syncthreads();
        if (t < 32) {
            float tm = (t < 8) ? red[t] : -1e30f;
            tm = warpMax(tm);
            if (t == 0) red[0] = tm;
        }
        __syncthreads();
        m = red[0];
        __syncthreads();

        v0 = __expf(v0 - m); v1 = __expf(v1 - m);
        v2 = __expf(v2 - m); v3 = __expf(v3 - m);
        float s = warpSum(v0 + v1 + v2 + v3);
        if ((t & 31) == 0) red[t >> 5] = s;
        __syncthreads();
        if (t < 32) {
            float ts = (t < 8) ? red[t] : 0.f;
            ts = warpSum(ts);
            if (t == 0) red[0] = ts;
        }
        __syncthreads();
        const float inv = 1.0f / red[0];
        __syncthreads();

        x[t] = v0 * inv; x[t + 256] = v1 * inv;
        x[t + 512] = v2 * inv; x[t + 768] = v3 * inv;
    }
}

// ============================================================================
// K3: deterministic two-stage column sums over a 65536 x 1024 panel.
// stage1: 256 blocks x 256 rows each -> g_part[256][1024]
// ============================================================================
__global__ __launch_bounds__(256) void colsum_stage1(
    const float* __restrict__ Xparam, int useLogits, int ld, int col0)
{
    const float* X = useLogits ? (const float*)g_logits : Xparam;
    const int p = blockIdx.x, t = threadIdx.x;
    float a0 = 0.f, a1 = 0.f, a2 = 0.f, a3 = 0.f;
    const float* base = X + (size_t)p * 256 * ld + col0;
    for (int r = 0; r < 256; ++r) {
        const float* row = base + (size_t)r * ld;
        a0 += row[t]; a1 += row[t + 256]; a2 += row[t + 512]; a3 += row[t + 768];
    }
    float* o = g_part + p * 1024;
    o[t] = a0; o[t + 256] = a1; o[t + 512] = a2; o[t + 768] = a3;
}

__global__ __launch_bounds__(256) void colsum_stage2(int dst, float scale)
{
    const int c = blockIdx.x * 256 + threadIdx.x;
    float s = 0.f;
    #pragma unroll 8
    for (int p = 0; p < 256; ++p) s += g_part[p * 1024 + c];
    s *= scale;
    if (dst == 0) g_cmean_h[c] = s; else g_wmean[c] = s;
}

// ============================================================================
// K4: c_vec[d] = mean(content) @ W_content + b_content   (tiny)
// ============================================================================
__global__ void project_cmean_kernel(const float* __restrict__ Wc,
                                     const float* __restrict__ bc)
{
    const int d = threadIdx.x;   // 128 threads
    float s = bc[d];
    #pragma unroll 4
    for (int h = 0; h < HDIM; ++h) s += g_cmean_h[h] * Wc[h * DDIM + d];
    g_cvec[d] = s;
}

// ============================================================================
// K5: read_content = read_weights @ memory   (65536 x 128, K=1024)
// read_weights live in g_logits cols [0,1024), ld = 2048.
// ============================================================================
__global__ __launch_bounds__(256) void gemm_read_kernel(
    const float* __restrict__ memory, float* __restrict__ outC)
{
    __shared__ float As[16][132];
    __shared__ float Bs[16][128];

    const int m0 = blockIdx.x * 128;
    const int tid = threadIdx.x;
    const int tx = tid & 15, ty = tid >> 4;

    const int arow = tid >> 2;
    const int acol = (tid & 3) * 4;
    const int brow = tid >> 5;
    const int bcol = (tid & 31) * 4;

    const float* Aptr = g_logits + (size_t)m0 * LODIM;

    float acc[8][8];
    #pragma unroll
    for (int i = 0; i < 8; ++i)
        #pragma unroll
        for (int j = 0; j < 8; ++j) acc[i][j] = 0.f;

    for (int k0 = 0; k0 < SDIM; k0 += 16) {
        #pragma unroll
        for (int h = 0; h < 2; ++h) {
            float4 v = *reinterpret_cast<const float4*>(
                Aptr + (size_t)(arow + 64 * h) * LODIM + k0 + acol);
            As[acol + 0][arow + 64 * h] = v.x;
            As[acol + 1][arow + 64 * h] = v.y;
            As[acol + 2][arow + 64 * h] = v.z;
            As[acol + 3][arow + 64 * h] = v.w;
        }
        #pragma unroll
        for (int h = 0; h < 2; ++h) {
            float4 v = *reinterpret_cast<const float4*>(
                memory + (size_t)(k0 + brow + 8 * h) * DDIM + bcol);
            *reinterpret_cast<float4*>(&Bs[brow + 8 * h][bcol]) = v;
        }
        __syncthreads();
        #pragma unroll
        for (int k = 0; k < 16; ++k) {
            float4 a0 = *reinterpret_cast<const float4*>(&As[k][ty * 8]);
            float4 a1 = *reinterpret_cast<const float4*>(&As[k][ty * 8 + 4]);
            float4 b0 = *reinterpret_cast<const float4*>(&Bs[k][tx * 8]);
            float4 b1 = *reinterpret_cast<const float4*>(&Bs[k][tx * 8 + 4]);
            float a[8] = {a0.x, a0.y, a0.z, a0.w, a1.x, a1.y, a1.z, a1.w};
            float b[8] = {b0.x, b0.y, b0.z, b0.w, b1.x, b1.y, b1.z, b1.w};
            #pragma unroll
            for (int i = 0; i < 8; ++i)
                #pragma unroll
                for (int j = 0; j < 8; ++j)
                    acc[i][j] += a[i] * b[j];
        }
        __syncthreads();
    }

    #pragma unroll
    for (int i = 0; i < 8; ++i) {
        float* orow = outC + (size_t)(m0 + ty * 8 + i) * DDIM + tx * 8;
        #pragma unroll
        for (int j = 0; j < 8; ++j) orow[j] = acc[i][j];
    }
}

// ============================================================================
// K6: memory / age update (tiny)
// ============================================================================
__global__ void update_kernel(const float* __restrict__ memory,
                              const float* __restrict__ age,
                              float* __restrict__ out_mem,
                              float* __restrict__ out_age)
{
    const int s = blockIdx.x;
    const int d = threadIdx.x;
    const float wm = g_wmean[s];
    const float a  = age[s];
    const bool mask = wm > 0.01f;
    const float cons = 1.0f / (1.0f + __expf(-a * 0.1f));
    const float f = mask ? wm * cons : 0.0f;
    const float m = memory[s * DDIM + d];
    out_mem[s * DDIM + d] = (1.0f - f) * m + f * g_cvec[d];
    if (d == 0) out_age[s] = a + (mask ? 1.0f : 0.0f);
}

// ============================================================================
extern "C" void kernel_launch(void* const* d_in, const int* in_sizes, int n_in,
                              void* d_out, int out_size)
{
    const float* query   = (const float*)d_in[0];
    const float* content = (const float*)d_in[1];
    const float* memory  = (const float*)d_in[2];
    const float* age     = (const float*)d_in[3];
    const float* W_read  = (const float*)d_in[4];
    const float* b_read  = (const float*)d_in[5];
    const float* W_write = (const float*)d_in[6];
    const float* b_write = (const float*)d_in[7];
    const float* W_cont  = (const float*)d_in[8];
    const float* b_cont  = (const float*)d_in[9];

    float* out      = (float*)d_out;
    float* out_read = out;                                   // [B, D]
    float* out_mem  = out + (size_t)BDIM * DDIM;             // [S, D]
    float* out_age  = out_mem + (size_t)SDIM * DDIM;         // [S]

    // content mean -> c_vec (mean before projection: algebraically identical)
    colsum_stage1<<<256, 256>>>(content, 0, HDIM, 0);
    colsum_stage2<<<4, 256>>>(0, 1.0f / (float)BDIM);
    project_cmean_kernel<<<1, 128>>>(W_cont, b_cont);

    // fused read+write logits GEMM, then per-row softmax (in place)
    gemm_logits_kernel<<<dim3(16, BDIM / 128), 256>>>(query, W_read, W_write,
                                                      b_read, b_write);
    softmax_kernel<<<BDIM, 256>>>();

    // mean write weights
    colsum_stage1<<<256, 256>>>(nullptr, 1, LODIM, SDIM);
    colsum_stage2<<<4, 256>>>(1, 1.0f / (float)BDIM);

    // read_content = read_weights @ memory
    gemm_read_kernel<<<BDIM / 128, 256>>>(memory, out_read);

    // memory + age update
    update_kernel<<<SDIM, DDIM>>>(memory, age, out_mem, out_age);
}

// round 5
// speedup vs baseline: 1.9572x; 1.9572x over previous
#include <cuda_runtime.h>
#include <cuda_bf16.h>
#include <cstdint>

// Problem dims
#define BDIM 65536
#define HDIM 1024
#define SDIM 1024
#define DDIM 128
#define LODIM 2048   // 2*SDIM : [read logits | write logits] per row

// ---------------- scratch (device globals: allocation-free rule) ----------------
__device__ float g_logits[(size_t)BDIM * LODIM];   // read half = raw logits; write half = softmaxed weights
__device__ float g_part[256 * 1024];               // partial column sums
__device__ float g_cmean_h[HDIM];
__device__ float g_wmean[SDIM];
__device__ float g_cvec[DDIM];
__device__ float g_bias[LODIM];                    // [b_read | b_write]

__device__ __nv_bfloat16 g_qh[(size_t)BDIM * HDIM];   // query hi      [B][H]
__device__ __nv_bfloat16 g_ql[(size_t)BDIM * HDIM];   // query lo
__device__ __nv_bfloat16 g_wth[(size_t)LODIM * HDIM]; // [Wr|Ww]^T hi  [N=2048][K=1024]
__device__ __nv_bfloat16 g_wtl[(size_t)LODIM * HDIM];
__device__ __nv_bfloat16 g_mth[(size_t)DDIM * SDIM];  // memory^T hi   [D=128][S=1024]
__device__ __nv_bfloat16 g_mtl[(size_t)DDIM * SDIM];
__device__ __nv_bfloat16 g_rwh[(size_t)BDIM * SDIM];  // read weights hi [B][S]
__device__ __nv_bfloat16 g_rwl[(size_t)BDIM * SDIM];

// ---------------- helpers ----------------
__device__ __forceinline__ uint32_t smem_u32(const void* p) {
    uint32_t a;
    asm("{ .reg .u64 t; cvta.to.shared.u64 t, %1; cvt.u32.u64 %0, t; }" : "=r"(a) : "l"(p));
    return a;
}
__device__ __forceinline__ uint32_t lds32(uint32_t a) {
    uint32_t v;
    asm volatile("ld.shared.b32 %0, [%1];" : "=r"(v) : "r"(a));
    return v;
}
__device__ __forceinline__ void mma16816(float* c, const uint32_t* a, const uint32_t* b) {
    asm volatile(
        "mma.sync.aligned.m16n8k16.row.col.f32.bf16.bf16.f32 "
        "{%0,%1,%2,%3}, {%4,%5,%6,%7}, {%8,%9}, {%0,%1,%2,%3};"
        : "+f"(c[0]), "+f"(c[1]), "+f"(c[2]), "+f"(c[3])
        : "r"(a[0]), "r"(a[1]), "r"(a[2]), "r"(a[3]), "r"(b[0]), "r"(b[1]));
}
__device__ __forceinline__ void cp16(uint32_t saddr, const void* g) {
    asm volatile("cp.async.cg.shared.global [%0], [%1], 16;" :: "r"(saddr), "l"(g));
}

__device__ __forceinline__ float warpMax(float v) {
    #pragma unroll
    for (int o = 16; o > 0; o >>= 1) v = fmaxf(v, __shfl_xor_sync(0xffffffffu, v, o));
    return v;
}
__device__ __forceinline__ float warpSum(float v) {
    #pragma unroll
    for (int o = 16; o > 0; o >>= 1) v += __shfl_xor_sync(0xffffffffu, v, o);
    return v;
}
__device__ __forceinline__ void split_bf16(float x, __nv_bfloat16& h, __nv_bfloat16& l) {
    h = __float2bfloat16_rn(x);
    l = __float2bfloat16_rn(x - __bfloat162float(h));
}

// ============================================================================
// Unified bf16x3 GEMM via mma.sync (HMMA path; no "a"-feature PTX needed).
// C[M,N] (+bias) = Ahi@Bhi^T + Ahi@Blo^T + Alo@Bhi^T, A:[M][1024], B:[N][1024].
// Operands selected DEVICE-SIDE by `which` (0: logits GEMM, 1: read GEMM) —
// __device__ globals must not be passed as host-side kernel args.
// CTA tile 128x128, BK=32, 2-stage cp.async double buffer.
// smem tile: [128 rows][32 cols] bf16, row stride 40 elems (80B) —
// conflict-free LDS.32 frag loads (banks (20r + c) mod 32 are a permutation).
// ============================================================================
#define TILE_B 10240           // one 128x32 tile (stride 40): 128*40*2
#define STAGE_B (4 * TILE_B)   // Ah | Al | Bh | Bl
#define GEMM_SMEM (2 * STAGE_B)

__global__ __launch_bounds__(256, 1) void gemm_mma(int which, float* __restrict__ Cout)
{
    extern __shared__ char sm[];
    const uint32_t sb = smem_u32(sm);
    const int tid = threadIdx.x, lane = tid & 31, wid = tid >> 5;
    const int wm = wid >> 2, wn = wid & 3;            // 2 x 4 warp grid
    const int m0 = blockIdx.y * 128, n0 = blockIdx.x * 128;

    const __nv_bfloat16 *Ah, *Al, *Bh, *Bl;
    float* C; int ldC; const float* bias;
    if (which == 0) {
        Ah = g_qh; Al = g_ql; Bh = g_wth; Bl = g_wtl;
        C = g_logits; ldC = LODIM; bias = g_bias;
    } else {
        Ah = g_rwh; Al = g_rwl; Bh = g_mth; Bl = g_mtl;
        C = Cout; ldC = DDIM; bias = nullptr;
    }

    float acc[4][4][4];
    #pragma unroll
    for (int i = 0; i < 4; ++i)
        #pragma unroll
        for (int j = 0; j < 4; ++j)
            #pragma unroll
            for (int k = 0; k < 4; ++k) acc[i][j][k] = 0.f;

    // chunk mapping for cp.async: 512 16B-chunks per tile, 2 per thread
    const int r_ld[2]  = { (tid + 0) >> 2, (tid + 256) >> 2 };
    const int c_ld[2]  = { (tid + 0) & 3,  (tid + 256) & 3 };

    auto load_stage = [&](int s, int k0) {
        const uint32_t base = sb + s * STAGE_B;
        const __nv_bfloat16* srcs[4] = { Ah, Al, Bh, Bl };
        #pragma unroll
        for (int t = 0; t < 4; ++t) {
            const __nv_bfloat16* g = srcs[t];
            const int row0 = (t < 2) ? m0 : n0;
            #pragma unroll
            for (int j = 0; j < 2; ++j) {
                const int r = r_ld[j], c = c_ld[j];
                cp16(base + t * TILE_B + r * 80 + c * 16,
                     g + (size_t)(row0 + r) * 1024 + k0 + c * 8);
            }
        }
        asm volatile("cp.async.commit_group;" ::: "memory");
    };

    load_stage(0, 0);

    const int rA = 64 * wm + (lane >> 2);
    const int rB = 32 * wn + (lane >> 2);
    const uint32_t cByte = (lane & 3) * 4;

    for (int c = 0; c < 32; ++c) {
        const int cur = c & 1;
        if (c + 1 < 32) {
            load_stage(cur ^ 1, (c + 1) * 32);
            asm volatile("cp.async.wait_group 1;" ::: "memory");
        } else {
            asm volatile("cp.async.wait_group 0;" ::: "memory");
        }
        __syncthreads();

        const uint32_t aH = sb + cur * STAGE_B;
        const uint32_t aL = aH + TILE_B;
        const uint32_t bH = aH + 2 * TILE_B;
        const uint32_t bL = aH + 3 * TILE_B;

        #pragma unroll
        for (int kk = 0; kk < 2; ++kk) {
            const uint32_t kOff = cByte + kk * 32;   // k16 block byte offset
            uint32_t fah[4][4], fal[4][4], fbh[4][2], fbl[4][2];
            #pragma unroll
            for (int mt = 0; mt < 4; ++mt) {
                const uint32_t ro = (uint32_t)(rA + 16 * mt) * 80 + kOff;
                fah[mt][0] = lds32(aH + ro);
                fah[mt][1] = lds32(aH + ro + 8 * 80);
                fah[mt][2] = lds32(aH + ro + 16);
                fah[mt][3] = lds32(aH + ro + 8 * 80 + 16);
                fal[mt][0] = lds32(aL + ro);
                fal[mt][1] = lds32(aL + ro + 8 * 80);
                fal[mt][2] = lds32(aL + ro + 16);
                fal[mt][3] = lds32(aL + ro + 8 * 80 + 16);
            }
            #pragma unroll
            for (int nt = 0; nt < 4; ++nt) {
                const uint32_t ro = (uint32_t)(rB + 8 * nt) * 80 + kOff;
                fbh[nt][0] = lds32(bH + ro);
                fbh[nt][1] = lds32(bH + ro + 16);
                fbl[nt][0] = lds32(bL + ro);
                fbl[nt][1] = lds32(bL + ro + 16);
            }
            #pragma unroll
            for (int mt = 0; mt < 4; ++mt)
                #pragma unroll
                for (int nt = 0; nt < 4; ++nt) {
                    mma16816(acc[mt][nt], fah[mt], fbh[nt]);
                    mma16816(acc[mt][nt], fah[mt], fbl[nt]);
                    mma16816(acc[mt][nt], fal[mt], fbh[nt]);
                }
        }
        __syncthreads();
    }

    // epilogue
    const bool hasB = (bias != nullptr);
    #pragma unroll
    for (int mt = 0; mt < 4; ++mt) {
        const int r0 = m0 + 64 * wm + 16 * mt + (lane >> 2);
        #pragma unroll
        for (int nt = 0; nt < 4; ++nt) {
            const int col = n0 + 32 * wn + 8 * nt + (lane & 3) * 2;
            float b0 = 0.f, b1 = 0.f;
            if (hasB) { b0 = bias[col]; b1 = bias[col + 1]; }
            float2 v0 = make_float2(acc[mt][nt][0] + b0, acc[mt][nt][1] + b1);
            float2 v1 = make_float2(acc[mt][nt][2] + b0, acc[mt][nt][3] + b1);
            *reinterpret_cast<float2*>(&C[(size_t)r0 * ldC + col]) = v0;
            *reinterpret_cast<float2*>(&C[(size_t)(r0 + 8) * ldC + col]) = v1;
        }
    }
}

// ============================================================================
// conversions
// ============================================================================
__global__ __launch_bounds__(256) void convert_q(const float* __restrict__ q) {
    size_t i = (size_t)blockIdx.x * 256 + threadIdx.x;   // float4 index
    float4 v = reinterpret_cast<const float4*>(q)[i];
    __nv_bfloat16 h[4], l[4];
    split_bf16(v.x, h[0], l[0]); split_bf16(v.y, h[1], l[1]);
    split_bf16(v.z, h[2], l[2]); split_bf16(v.w, h[3], l[3]);
    *reinterpret_cast<ushort4*>(g_qh + i * 4) =
        make_ushort4(__bfloat16_as_ushort(h[0]), __bfloat16_as_ushort(h[1]),
                     __bfloat16_as_ushort(h[2]), __bfloat16_as_ushort(h[3]));
    *reinterpret_cast<ushort4*>(g_ql + i * 4) =
        make_ushort4(__bfloat16_as_ushort(l[0]), __bfloat16_as_ushort(l[1]),
                     __bfloat16_as_ushort(l[2]), __bfloat16_as_ushort(l[3]));
}

__global__ __launch_bounds__(256) void convert_w(const float* __restrict__ Wr,
                                                 const float* __restrict__ Ww) {
    size_t id = (size_t)blockIdx.x * 256 + threadIdx.x;   // 2048*1024
    int n = (int)(id >> 10), k = (int)(id & 1023);
    float x = (n < SDIM) ? Wr[(size_t)k * SDIM + n] : Ww[(size_t)k * SDIM + (n - SDIM)];
    __nv_bfloat16 h, l; split_bf16(x, h, l);
    g_wth[id] = h; g_wtl[id] = l;
}

__global__ __launch_bounds__(256) void convert_mem(const float* __restrict__ mem) {
    size_t id = (size_t)blockIdx.x * 256 + threadIdx.x;   // 128*1024
    int d = (int)(id >> 10), s = (int)(id & 1023);
    float x = mem[(size_t)s * DDIM + d];
    __nv_bfloat16 h, l; split_bf16(x, h, l);
    g_mth[id] = h; g_mtl[id] = l;
}

__global__ __launch_bounds__(256) void prep_bias(const float* __restrict__ br,
                                                 const float* __restrict__ bw) {
    int i = blockIdx.x * 256 + threadIdx.x;
    g_bias[i] = (i < SDIM) ? br[i] : bw[i - SDIM];
}

// ============================================================================
// softmax: read half -> bf16 hi/lo weights (GEMM2 A); write half -> fp32 in place
// ============================================================================
__global__ __launch_bounds__(256) void softmax_kernel() {
    __shared__ float red[8];
    float* base = g_logits + (size_t)blockIdx.x * LODIM;
    const int t = threadIdx.x;

    #pragma unroll
    for (int half = 0; half < 2; ++half) {
        float* x = base + half * SDIM;
        float v0 = x[t], v1 = x[t + 256], v2 = x[t + 512], v3 = x[t + 768];

        float m = fmaxf(fmaxf(v0, v1), fmaxf(v2, v3));
        m = warpMax(m);
        if ((t & 31) == 0) red[t >> 5] = m;
        __syncthreads();
        if (t < 32) {
            float tm = (t < 8) ? red[t] : -1e30f;
            tm = warpMax(tm);
            if (t == 0) red[0] = tm;
        }
        __syncthreads();
        m = red[0];
        __syncthreads();

        v0 = __expf(v0 - m); v1 = __expf(v1 - m);
        v2 = __expf(v2 - m); v3 = __expf(v3 - m);
        float sum = warpSum(v0 + v1 + v2 + v3);
        if ((t & 31) == 0) red[t >> 5] = sum;
        __syncthreads();
        if (t < 32) {
            float ts = (t < 8) ? red[t] : 0.f;
            ts = warpSum(ts);
            if (t == 0) red[0] = ts;
        }
        __syncthreads();
        const float inv = 1.0f / red[0];
        __syncthreads();

        v0 *= inv; v1 *= inv; v2 *= inv; v3 *= inv;
        if (half == 0) {
            __nv_bfloat16* wh = g_rwh + (size_t)blockIdx.x * SDIM;
            __nv_bfloat16* wl = g_rwl + (size_t)blockIdx.x * SDIM;
            __nv_bfloat16 h, l;
            split_bf16(v0, h, l); wh[t] = h;       wl[t] = l;
            split_bf16(v1, h, l); wh[t + 256] = h; wl[t + 256] = l;
            split_bf16(v2, h, l); wh[t + 512] = h; wl[t + 512] = l;
            split_bf16(v3, h, l); wh[t + 768] = h; wl[t + 768] = l;
        } else {
            x[t] = v0; x[t + 256] = v1; x[t + 512] = v2; x[t + 768] = v3;
        }
    }
}

// ============================================================================
// deterministic two-stage column sums (65536 x 1024 panel)
// ============================================================================
__global__ __launch_bounds__(256) void colsum_stage1(
    const float* __restrict__ Xparam, int useLogits, int ld, int col0) {
    const float* X = useLogits ? (const float*)g_logits : Xparam;
    const int p = blockIdx.x, t = threadIdx.x;
    float a0 = 0.f, a1 = 0.f, a2 = 0.f, a3 = 0.f;
    const float* base = X + (size_t)p * 256 * ld + col0;
    for (int r = 0; r < 256; ++r) {
        const float* row = base + (size_t)r * ld;
        a0 += row[t]; a1 += row[t + 256]; a2 += row[t + 512]; a3 += row[t + 768];
    }
    float* o = g_part + p * 1024;
    o[t] = a0; o[t + 256] = a1; o[t + 512] = a2; o[t + 768] = a3;
}

__global__ __launch_bounds__(256) void colsum_stage2(int dst, float scale) {
    const int c = blockIdx.x * 256 + threadIdx.x;
    float s = 0.f;
    #pragma unroll 8
    for (int p = 0; p < 256; ++p) s += g_part[p * 1024 + c];
    s *= scale;
    if (dst == 0) g_cmean_h[c] = s; else g_wmean[c] = s;
}

__global__ void project_cmean_kernel(const float* __restrict__ Wc,
                                     const float* __restrict__ bc) {
    const int d = threadIdx.x;   // 128 threads
    float s = bc[d];
    #pragma unroll 4
    for (int h = 0; h < HDIM; ++h) s += g_cmean_h[h] * Wc[h * DDIM + d];
    g_cvec[d] = s;
}

__global__ void update_kernel(const float* __restrict__ memory,
                              const float* __restrict__ age,
                              float* __restrict__ out_mem,
                              float* __restrict__ out_age) {
    const int s = blockIdx.x;
    const int d = threadIdx.x;
    const float wm = g_wmean[s];
    const float a  = age[s];
    const bool mask = wm > 0.01f;
    const float cons = 1.0f / (1.0f + __expf(-a * 0.1f));
    const float f = mask ? wm * cons : 0.0f;
    const float m = memory[s * DDIM + d];
    out_mem[s * DDIM + d] = (1.0f - f) * m + f * g_cvec[d];
    if (d == 0) out_age[s] = a + (mask ? 1.0f : 0.0f);
}

// ============================================================================
extern "C" void kernel_launch(void* const* d_in, const int* in_sizes, int n_in,
                              void* d_out, int out_size) {
    const float* query   = (const float*)d_in[0];
    const float* content = (const float*)d_in[1];
    const float* memory  = (const float*)d_in[2];
    const float* age     = (const float*)d_in[3];
    const float* W_read  = (const float*)d_in[4];
    const float* b_read  = (const float*)d_in[5];
    const float* W_write = (const float*)d_in[6];
    const float* b_write = (const float*)d_in[7];
    const float* W_cont  = (const float*)d_in[8];
    const float* b_cont  = (const float*)d_in[9];

    float* out      = (float*)d_out;
    float* out_read = out;                                   // [B, D]
    float* out_mem  = out + (size_t)BDIM * DDIM;             // [S, D]
    float* out_age  = out_mem + (size_t)SDIM * DDIM;         // [S]

    cudaFuncSetAttribute(gemm_mma, cudaFuncAttributeMaxDynamicSharedMemorySize, GEMM_SMEM);

    // bf16 hi/lo conversions
    convert_q<<<65536, 256>>>(query);
    convert_w<<<8192, 256>>>(W_read, W_write);
    convert_mem<<<512, 256>>>(memory);
    prep_bias<<<8, 256>>>(b_read, b_write);

    // content mean -> c_vec (mean before projection: algebraically identical)
    colsum_stage1<<<256, 256>>>(content, 0, HDIM, 0);
    colsum_stage2<<<4, 256>>>(0, 1.0f / (float)BDIM);
    project_cmean_kernel<<<1, 128>>>(W_cont, b_cont);

    // GEMM1: logits = Q @ [Wr|Ww] + bias  (bf16x3 on tensor cores)
    gemm_mma<<<dim3(16, BDIM / 128), 256, GEMM_SMEM>>>(0, nullptr);

    softmax_kernel<<<BDIM, 256>>>();

    // mean write weights (fp32 write-half of g_logits)
    colsum_stage1<<<256, 256>>>(nullptr, 1, LODIM, SDIM);
    colsum_stage2<<<4, 256>>>(1, 1.0f / (float)BDIM);

    // GEMM2: read_content = read_weights @ memory (bf16x3 on tensor cores)
    gemm_mma<<<dim3(1, BDIM / 128), 256, GEMM_SMEM>>>(1, out_read);

    // memory + age update
    update_kernel<<<SDIM, DDIM>>>(memory, age, out_mem, out_age);
}

// round 6
// speedup vs baseline: 1.9941x; 1.0189x over previous
#include <cuda_runtime.h>
#include <cuda_bf16.h>
#include <cstdint>

// Problem dims
#define BDIM 65536
#define HDIM 1024
#define SDIM 1024
#define DDIM 128
#define LODIM 2048   // 2*SDIM : [read logits | write logits] per row

// ---------------- scratch (device globals: allocation-free rule) ----------------
__device__ float g_logits[(size_t)BDIM * LODIM];   // read half = raw logits; write half = softmaxed weights
__device__ float g_part[256 * 1024];               // partial column sums
__device__ float g_cmean_h[HDIM];
__device__ float g_wmean[SDIM];
__device__ float g_cvec[DDIM];
__device__ float g_bias[LODIM];                    // [b_read | b_write]

__device__ __nv_bfloat16 g_qh[(size_t)BDIM * HDIM];   // query hi      [B][H]
__device__ __nv_bfloat16 g_ql[(size_t)BDIM * HDIM];   // query lo
__device__ __nv_bfloat16 g_wth[(size_t)LODIM * HDIM]; // [Wr|Ww]^T hi  [N=2048][K=1024]
__device__ __nv_bfloat16 g_wtl[(size_t)LODIM * HDIM];
__device__ __nv_bfloat16 g_mth[(size_t)DDIM * SDIM];  // memory^T hi   [D=128][S=1024]
__device__ __nv_bfloat16 g_mtl[(size_t)DDIM * SDIM];
__device__ __nv_bfloat16 g_rwh[(size_t)BDIM * SDIM];  // read weights hi [B][S]
__device__ __nv_bfloat16 g_rwl[(size_t)BDIM * SDIM];

// ---------------- helpers ----------------
__device__ __forceinline__ uint32_t smem_u32(const void* p) {
    uint32_t a;
    asm("{ .reg .u64 t; cvta.to.shared.u64 t, %1; cvt.u32.u64 %0, t; }" : "=r"(a) : "l"(p));
    return a;
}
__device__ __forceinline__ void ldsm_x4(uint32_t* r, uint32_t addr) {
    asm volatile("ldmatrix.sync.aligned.m8n8.x4.shared.b16 {%0,%1,%2,%3}, [%4];"
                 : "=r"(r[0]), "=r"(r[1]), "=r"(r[2]), "=r"(r[3]) : "r"(addr));
}
__device__ __forceinline__ void mma16816(float* c, const uint32_t* a, const uint32_t* b) {
    asm volatile(
        "mma.sync.aligned.m16n8k16.row.col.f32.bf16.bf16.f32 "
        "{%0,%1,%2,%3}, {%4,%5,%6,%7}, {%8,%9}, {%0,%1,%2,%3};"
        : "+f"(c[0]), "+f"(c[1]), "+f"(c[2]), "+f"(c[3])
        : "r"(a[0]), "r"(a[1]), "r"(a[2]), "r"(a[3]), "r"(b[0]), "r"(b[1]));
}
__device__ __forceinline__ void cp16(uint32_t saddr, const void* g) {
    asm volatile("cp.async.cg.shared.global [%0], [%1], 16;" :: "r"(saddr), "l"(g));
}

__device__ __forceinline__ float warpMax(float v) {
    #pragma unroll
    for (int o = 16; o > 0; o >>= 1) v = fmaxf(v, __shfl_xor_sync(0xffffffffu, v, o));
    return v;
}
__device__ __forceinline__ float warpSum(float v) {
    #pragma unroll
    for (int o = 16; o > 0; o >>= 1) v += __shfl_xor_sync(0xffffffffu, v, o);
    return v;
}
__device__ __forceinline__ void split_bf16(float x, __nv_bfloat16& h, __nv_bfloat16& l) {
    h = __float2bfloat16_rn(x);
    l = __float2bfloat16_rn(x - __bfloat162float(h));
}

// ============================================================================
// Unified bf16x3 GEMM via mma.sync + ldmatrix, 3-stage cp.async pipeline.
// C[M,N] (+bias) = Ahi@Bhi^T + Ahi@Blo^T + Alo@Bhi^T, A:[M][1024], B:[N][1024].
// Operands selected DEVICE-SIDE by `which` (0: logits GEMM, 1: read GEMM).
// CTA tile 128x128, BK=32. smem tile: [128 rows][32 cols] bf16, row stride
// 40 elems (80B) — conflict-free for both cp.async stores and ldmatrix phases
// (bank groups (20r) mod 32 are a permutation of 4-bank groups).
// ============================================================================
#define TILE_B 10240           // one 128x32 tile (stride 40): 128*40*2
#define STAGE_B (4 * TILE_B)   // Ah | Al | Bh | Bl
#define NSTAGE 3
#define GEMM_SMEM (NSTAGE * STAGE_B)

__global__ __launch_bounds__(256, 1) void gemm_mma(int which, float* __restrict__ Cout)
{
    extern __shared__ char sm[];
    const uint32_t sb = smem_u32(sm);
    const int tid = threadIdx.x, lane = tid & 31, wid = tid >> 5;
    const int wm = wid >> 2, wn = wid & 3;            // 2 x 4 warp grid
    const int m0 = blockIdx.y * 128, n0 = blockIdx.x * 128;

    const __nv_bfloat16 *Ah, *Al, *Bh, *Bl;
    float* C; int ldC; const float* bias;
    if (which == 0) {
        Ah = g_qh; Al = g_ql; Bh = g_wth; Bl = g_wtl;
        C = g_logits; ldC = LODIM; bias = g_bias;
    } else {
        Ah = g_rwh; Al = g_rwl; Bh = g_mth; Bl = g_mtl;
        C = Cout; ldC = DDIM; bias = nullptr;
    }

    float acc[4][4][4];
    #pragma unroll
    for (int i = 0; i < 4; ++i)
        #pragma unroll
        for (int j = 0; j < 4; ++j)
            #pragma unroll
            for (int k = 0; k < 4; ++k) acc[i][j][k] = 0.f;

    // cp.async chunk mapping: 512 16B-chunks per tile, 2 per thread
    const int r_ld[2]  = { (tid + 0) >> 2, (tid + 256) >> 2 };
    const int c_ld[2]  = { (tid + 0) & 3,  (tid + 256) & 3 };

    auto load_stage = [&](int s, int k0) {
        const uint32_t base = sb + s * STAGE_B;
        const __nv_bfloat16* srcs[4] = { Ah, Al, Bh, Bl };
        #pragma unroll
        for (int t = 0; t < 4; ++t) {
            const __nv_bfloat16* g = srcs[t];
            const int row0 = (t < 2) ? m0 : n0;
            #pragma unroll
            for (int j = 0; j < 2; ++j) {
                const int r = r_ld[j], c = c_ld[j];
                cp16(base + t * TILE_B + r * 80 + c * 16,
                     g + (size_t)(row0 + r) * 1024 + k0 + c * 8);
            }
        }
        asm volatile("cp.async.commit_group;" ::: "memory");
    };

    // ldmatrix per-lane address components
    const int lane8 = lane & 7, laneT = lane >> 3;    // tile index 0..3
    // A x4 tiles: t0=(r0-7,kLo) t1=(r8-15,kLo) t2=(r0-7,kHi) t3=(r8-15,kHi)
    const uint32_t aRow = 64 * wm + lane8 + 8 * (laneT & 1);
    const uint32_t aCol = 16 * (laneT >> 1);
    // B x4 tiles (covers nt pair): t0=(nt,kLo) t1=(nt,kHi) t2=(nt+1,kLo) t3=(nt+1,kHi)
    const uint32_t bRow = 32 * wn + lane8 + 8 * (laneT >> 1);
    const uint32_t bCol = 16 * (laneT & 1);

    load_stage(0, 0);
    load_stage(1, 32);

    for (int c = 0; c < 32; ++c) {
        if (c < 31) asm volatile("cp.async.wait_group 1;" ::: "memory");
        else        asm volatile("cp.async.wait_group 0;" ::: "memory");
        __syncthreads();
        if (c + 2 < 32) load_stage((c + 2) % NSTAGE, (c + 2) * 32);

        const uint32_t aH = sb + (c % NSTAGE) * STAGE_B;
        const uint32_t aL = aH + TILE_B;
        const uint32_t bH = aH + 2 * TILE_B;
        const uint32_t bL = aH + 3 * TILE_B;

        #pragma unroll
        for (int kk = 0; kk < 2; ++kk) {
            const uint32_t kb = kk * 32;
            uint32_t fah[4][4], fal[4][4], fbh[2][4], fbl[2][4];
            #pragma unroll
            for (int mt = 0; mt < 4; ++mt) {
                const uint32_t ro = (aRow + 16 * mt) * 80 + aCol + kb;
                ldsm_x4(fah[mt], aH + ro);
                ldsm_x4(fal[mt], aL + ro);
            }
            #pragma unroll
            for (int np = 0; np < 2; ++np) {
                const uint32_t ro = (bRow + 16 * np) * 80 + bCol + kb;
                ldsm_x4(fbh[np], bH + ro);
                ldsm_x4(fbl[np], bL + ro);
            }
            #pragma unroll
            for (int mt = 0; mt < 4; ++mt)
                #pragma unroll
                for (int nt = 0; nt < 4; ++nt) {
                    const uint32_t* bh = &fbh[nt >> 1][(nt & 1) * 2];
                    const uint32_t* bl = &fbl[nt >> 1][(nt & 1) * 2];
                    mma16816(acc[mt][nt], fah[mt], bh);
                    mma16816(acc[mt][nt], fah[mt], bl);
                    mma16816(acc[mt][nt], fal[mt], bh);
                }
        }
        __syncthreads();
    }

    // epilogue
    const bool hasB = (bias != nullptr);
    #pragma unroll
    for (int mt = 0; mt < 4; ++mt) {
        const int r0 = m0 + 64 * wm + 16 * mt + (lane >> 2);
        #pragma unroll
        for (int nt = 0; nt < 4; ++nt) {
            const int col = n0 + 32 * wn + 8 * nt + (lane & 3) * 2;
            float b0 = 0.f, b1 = 0.f;
            if (hasB) { b0 = bias[col]; b1 = bias[col + 1]; }
            float2 v0 = make_float2(acc[mt][nt][0] + b0, acc[mt][nt][1] + b1);
            float2 v1 = make_float2(acc[mt][nt][2] + b0, acc[mt][nt][3] + b1);
            *reinterpret_cast<float2*>(&C[(size_t)r0 * ldC + col]) = v0;
            *reinterpret_cast<float2*>(&C[(size_t)(r0 + 8) * ldC + col]) = v1;
        }
    }
}

// ============================================================================
// conversions
// ============================================================================
__global__ __launch_bounds__(256) void convert_q(const float* __restrict__ q) {
    size_t i = (size_t)blockIdx.x * 256 + threadIdx.x;   // float4 index
    float4 v = reinterpret_cast<const float4*>(q)[i];
    __nv_bfloat16 h[4], l[4];
    split_bf16(v.x, h[0], l[0]); split_bf16(v.y, h[1], l[1]);
    split_bf16(v.z, h[2], l[2]); split_bf16(v.w, h[3], l[3]);
    *reinterpret_cast<ushort4*>(g_qh + i * 4) =
        make_ushort4(__bfloat16_as_ushort(h[0]), __bfloat16_as_ushort(h[1]),
                     __bfloat16_as_ushort(h[2]), __bfloat16_as_ushort(h[3]));
    *reinterpret_cast<ushort4*>(g_ql + i * 4) =
        make_ushort4(__bfloat16_as_ushort(l[0]), __bfloat16_as_ushort(l[1]),
                     __bfloat16_as_ushort(l[2]), __bfloat16_as_ushort(l[3]));
}

__global__ __launch_bounds__(256) void convert_w(const float* __restrict__ Wr,
                                                 const float* __restrict__ Ww) {
    size_t id = (size_t)blockIdx.x * 256 + threadIdx.x;   // 2048*1024
    int n = (int)(id >> 10), k = (int)(id & 1023);
    float x = (n < SDIM) ? Wr[(size_t)k * SDIM + n] : Ww[(size_t)k * SDIM + (n - SDIM)];
    __nv_bfloat16 h, l; split_bf16(x, h, l);
    g_wth[id] = h; g_wtl[id] = l;
}

__global__ __launch_bounds__(256) void convert_mem(const float* __restrict__ mem) {
    size_t id = (size_t)blockIdx.x * 256 + threadIdx.x;   // 128*1024
    int d = (int)(id >> 10), s = (int)(id & 1023);
    float x = mem[(size_t)s * DDIM + d];
    __nv_bfloat16 h, l; split_bf16(x, h, l);
    g_mth[id] = h; g_mtl[id] = l;
}

__global__ __launch_bounds__(256) void prep_bias(const float* __restrict__ br,
                                                 const float* __restrict__ bw) {
    int i = blockIdx.x * 256 + threadIdx.x;
    g_bias[i] = (i < SDIM) ? br[i] : bw[i - SDIM];
}

// ============================================================================
// softmax: read half -> bf16 hi/lo weights (GEMM2 A); write half -> fp32 in place
// ============================================================================
__global__ __launch_bounds__(256) void softmax_kernel() {
    __shared__ float red[8];
    float* base = g_logits + (size_t)blockIdx.x * LODIM;
    const int t = threadIdx.x;

    #pragma unroll
    for (int half = 0; half < 2; ++half) {
        float* x = base + half * SDIM;
        float v0 = x[t], v1 = x[t + 256], v2 = x[t + 512], v3 = x[t + 768];

        float m = fmaxf(fmaxf(v0, v1), fmaxf(v2, v3));
        m = warpMax(m);
        if ((t & 31) == 0) red[t >> 5] = m;
        __syncthreads();
        if (t < 32) {
            float tm = (t < 8) ? red[t] : -1e30f;
            tm = warpMax(tm);
            if (t == 0) red[0] = tm;
        }
        __syncthreads();
        m = red[0];
        __syncthreads();

        v0 = __expf(v0 - m); v1 = __expf(v1 - m);
        v2 = __expf(v2 - m); v3 = __expf(v3 - m);
        float sum = warpSum(v0 + v1 + v2 + v3);
        if ((t & 31) == 0) red[t >> 5] = sum;
        __syncthreads();
        if (t < 32) {
            float ts = (t < 8) ? red[t] : 0.f;
            ts = warpSum(ts);
            if (t == 0) red[0] = ts;
        }
        __syncthreads();
        const float inv = 1.0f / red[0];
        __syncthreads();

        v0 *= inv; v1 *= inv; v2 *= inv; v3 *= inv;
        if (half == 0) {
            __nv_bfloat16* wh = g_rwh + (size_t)blockIdx.x * SDIM;
            __nv_bfloat16* wl = g_rwl + (size_t)blockIdx.x * SDIM;
            __nv_bfloat16 h, l;
            split_bf16(v0, h, l); wh[t] = h;       wl[t] = l;
            split_bf16(v1, h, l); wh[t + 256] = h; wl[t + 256] = l;
            split_bf16(v2, h, l); wh[t + 512] = h; wl[t + 512] = l;
            split_bf16(v3, h, l); wh[t + 768] = h; wl[t + 768] = l;
        } else {
            x[t] = v0; x[t + 256] = v1; x[t + 512] = v2; x[t + 768] = v3;
        }
    }
}

// ============================================================================
// deterministic two-stage column sums (65536 x 1024 panel)
// ============================================================================
__global__ __launch_bounds__(256) void colsum_stage1(
    const float* __restrict__ Xparam, int useLogits, int ld, int col0) {
    const float* X = useLogits ? (const float*)g_logits : Xparam;
    const int p = blockIdx.x, t = threadIdx.x;
    float a0 = 0.f, a1 = 0.f, a2 = 0.f, a3 = 0.f;
    const float* base = X + (size_t)p * 256 * ld + col0;
    for (int r = 0; r < 256; ++r) {
        const float* row = base + (size_t)r * ld;
        a0 += row[t]; a1 += row[t + 256]; a2 += row[t + 512]; a3 += row[t + 768];
    }
    float* o = g_part + p * 1024;
    o[t] = a0; o[t + 256] = a1; o[t + 512] = a2; o[t + 768] = a3;
}

__global__ __launch_bounds__(256) void colsum_stage2(int dst, float scale) {
    const int c = blockIdx.x * 256 + threadIdx.x;
    float s = 0.f;
    #pragma unroll 8
    for (int p = 0; p < 256; ++p) s += g_part[p * 1024 + c];
    s *= scale;
    if (dst == 0) g_cmean_h[c] = s; else g_wmean[c] = s;
}

__global__ void project_cmean_kernel(const float* __restrict__ Wc,
                                     const float* __restrict__ bc) {
    const int d = threadIdx.x;   // 128 threads
    float s = bc[d];
    #pragma unroll 4
    for (int h = 0; h < HDIM; ++h) s += g_cmean_h[h] * Wc[h * DDIM + d];
    g_cvec[d] = s;
}

__global__ void update_kernel(const float* __restrict__ memory,
                              const float* __restrict__ age,
                              float* __restrict__ out_mem,
                              float* __restrict__ out_age) {
    const int s = blockIdx.x;
    const int d = threadIdx.x;
    const float wm = g_wmean[s];
    const float a  = age[s];
    const bool mask = wm > 0.01f;
    const float cons = 1.0f / (1.0f + __expf(-a * 0.1f));
    const float f = mask ? wm * cons : 0.0f;
    const float m = memory[s * DDIM + d];
    out_mem[s * DDIM + d] = (1.0f - f) * m + f * g_cvec[d];
    if (d == 0) out_age[s] = a + (mask ? 1.0f : 0.0f);
}

// ============================================================================
extern "C" void kernel_launch(void* const* d_in, const int* in_sizes, int n_in,
                              void* d_out, int out_size) {
    const float* query   = (const float*)d_in[0];
    const float* content = (const float*)d_in[1];
    const float* memory  = (const float*)d_in[2];
    const float* age     = (const float*)d_in[3];
    const float* W_read  = (const float*)d_in[4];
    const float* b_read  = (const float*)d_in[5];
    const float* W_write = (const float*)d_in[6];
    const float* b_write = (const float*)d_in[7];
    const float* W_cont  = (const float*)d_in[8];
    const float* b_cont  = (const float*)d_in[9];

    float* out      = (float*)d_out;
    float* out_read = out;                                   // [B, D]
    float* out_mem  = out + (size_t)BDIM * DDIM;             // [S, D]
    float* out_age  = out_mem + (size_t)SDIM * DDIM;         // [S]

    cudaFuncSetAttribute(gemm_mma, cudaFuncAttributeMaxDynamicSharedMemorySize, GEMM_SMEM);

    // bf16 hi/lo conversions
    convert_q<<<65536, 256>>>(query);
    convert_w<<<8192, 256>>>(W_read, W_write);
    convert_mem<<<512, 256>>>(memory);
    prep_bias<<<8, 256>>>(b_read, b_write);

    // content mean -> c_vec (mean before projection: algebraically identical)
    colsum_stage1<<<256, 256>>>(content, 0, HDIM, 0);
    colsum_stage2<<<4, 256>>>(0, 1.0f / (float)BDIM);
    project_cmean_kernel<<<1, 128>>>(W_cont, b_cont);

    // GEMM1: logits = Q @ [Wr|Ww] + bias  (bf16x3 on tensor cores)
    gemm_mma<<<dim3(16, BDIM / 128), 256, GEMM_SMEM>>>(0, nullptr);

    softmax_kernel<<<BDIM, 256>>>();

    // mean write weights (fp32 write-half of g_logits)
    colsum_stage1<<<256, 256>>>(nullptr, 1, LODIM, SDIM);
    colsum_stage2<<<4, 256>>>(1, 1.0f / (float)BDIM);

    // GEMM2: read_content = read_weights @ memory (bf16x3 on tensor cores)
    gemm_mma<<<dim3(1, BDIM / 128), 256, GEMM_SMEM>>>(1, out_read);

    // memory + age update
    update_kernel<<<SDIM, DDIM>>>(memory, age, out_mem, out_age);
}